// round 4
// baseline (speedup 1.0000x reference)
#include <cuda_runtime.h>
#include <cuda_bf16.h>
#include <cstdint>

// Problem constants (shape-specific problem)
#define B_   64
#define T_   1000
#define I_   512
#define O_   256
#define M_   (B_ * T_)          // 64000
#define ALPHA 0.95f
#define BETA  0.9f

// GEMM tiling
#define BM 128
#define BN 128
#define BK 16
#define KTILES (I_ / BK)        // 32
#define PAD 4
#define LDA (BM + PAD)          // 132
#define LDB (BN + PAD)          // 132

// Scratch for h = inputs @ W^T  : 64000 x 256 floats = 65.5 MB (static, no alloc)
__device__ float g_h[(size_t)M_ * O_];

// ---------------------------------------------------------------------------
// GEMM: C[M,N] = A[M,K] * W[N,K]^T   (both K-contiguous, K-major)
// 128x128x16 CTA tile, 256 threads, 8x8 per-thread micro-tile,
// packed fma.rn.f32x2 inner loop (2 FMAs/instr), register-prefetch pipeline.
// ---------------------------------------------------------------------------
__global__ __launch_bounds__(256, 2)
void snn_gemm_kernel(const float* __restrict__ A, const float* __restrict__ W)
{
    __shared__ float As[BK][LDA];
    __shared__ float Bs[BK][LDB];

    const int tid = threadIdx.x;
    const int m0  = blockIdx.y * BM;
    const int n0  = blockIdx.x * BN;

    // Loader mapping: 512 float4 per tile per operand; each thread loads 2.
    const int idx0 = tid;          // float4 index 0
    const int idx1 = tid + 256;    // float4 index 1
    const int rowA0 = idx0 >> 2, c40 = (idx0 & 3) * 4;
    const int rowA1 = idx1 >> 2, c41 = (idx1 & 3) * 4;

    const float4* Ag0 = (const float4*)(A + (size_t)(m0 + rowA0) * I_ + c40);
    const float4* Ag1 = (const float4*)(A + (size_t)(m0 + rowA1) * I_ + c41);
    const float4* Wg0 = (const float4*)(W + (size_t)(n0 + rowA0) * I_ + c40);
    const float4* Wg1 = (const float4*)(W + (size_t)(n0 + rowA1) * I_ + c41);

    // Compute mapping
    const int ty = tid >> 4;           // 0..15
    const int tx = tid & 15;           // 0..15
    const int mo = ty * 8;
    const int no = tx * 8;

    unsigned long long acc[8][4];
    #pragma unroll
    for (int m = 0; m < 8; m++)
        #pragma unroll
        for (int j = 0; j < 4; j++) acc[m][j] = 0ull;

    // prologue: load k-tile 0
    float4 ra0 = Ag0[0];
    float4 ra1 = Ag1[0];
    float4 rb0 = Wg0[0];
    float4 rb1 = Wg1[0];

    #pragma unroll 1
    for (int kt = 0; kt < KTILES; kt++) {
        // stash regs -> smem
        As[c40 + 0][rowA0] = ra0.x; As[c40 + 1][rowA0] = ra0.y;
        As[c40 + 2][rowA0] = ra0.z; As[c40 + 3][rowA0] = ra0.w;
        As[c41 + 0][rowA1] = ra1.x; As[c41 + 1][rowA1] = ra1.y;
        As[c41 + 2][rowA1] = ra1.z; As[c41 + 3][rowA1] = ra1.w;
        Bs[c40 + 0][rowA0] = rb0.x; Bs[c40 + 1][rowA0] = rb0.y;
        Bs[c40 + 2][rowA0] = rb0.z; Bs[c40 + 3][rowA0] = rb0.w;
        Bs[c41 + 0][rowA1] = rb1.x; Bs[c41 + 1][rowA1] = rb1.y;
        Bs[c41 + 2][rowA1] = rb1.z; Bs[c41 + 3][rowA1] = rb1.w;
        __syncthreads();

        // prefetch next k-tile while computing this one
        if (kt + 1 < KTILES) {
            const int koff = (kt + 1) * (BK / 4);   // in float4 units
            ra0 = Ag0[koff]; ra1 = Ag1[koff];
            rb0 = Wg0[koff]; rb1 = Wg1[koff];
        }

        #pragma unroll
        for (int k = 0; k < BK; k++) {
            float4 a0 = *(const float4*)(&As[k][mo]);
            float4 a1 = *(const float4*)(&As[k][mo + 4]);
            float av[8] = {a0.x, a0.y, a0.z, a0.w, a1.x, a1.y, a1.z, a1.w};

            unsigned long long a2[8];
            #pragma unroll
            for (int m = 0; m < 8; m++)
                asm("mov.b64 %0, {%1, %1};" : "=l"(a2[m]) : "f"(av[m]));

            unsigned long long b2[4];
            #pragma unroll
            for (int j = 0; j < 4; j++)
                b2[j] = *(const unsigned long long*)(&Bs[k][no + 2 * j]);

            #pragma unroll
            for (int m = 0; m < 8; m++)
                #pragma unroll
                for (int j = 0; j < 4; j++)
                    asm("fma.rn.f32x2 %0, %1, %2, %3;"
                        : "=l"(acc[m][j])
                        : "l"(a2[m]), "l"(b2[j]), "l"(acc[m][j]));
        }
        __syncthreads();
    }

    // epilogue: unpack + store
    #pragma unroll
    for (int m = 0; m < 8; m++) {
        float c[8];
        #pragma unroll
        for (int j = 0; j < 4; j++)
            asm("mov.b64 {%0, %1}, %2;"
                : "=f"(c[2 * j]), "=f"(c[2 * j + 1]) : "l"(acc[m][j]));
        float* cp = g_h + (size_t)(m0 + mo + m) * O_ + n0 + no;
        *(float4*)(cp + 0) = make_float4(c[0], c[1], c[2], c[3]);
        *(float4*)(cp + 4) = make_float4(c[4], c[5], c[6], c[7]);
    }
}

// ---------------------------------------------------------------------------
// Scan: per (b,o) chain over T. out_t = BETA*out + flt_old ; flt = ALPHA*flt + h_t
// One thread per (b,o); o contiguous -> coalesced 128B/warp. Unroll 4 for MLP.
// ---------------------------------------------------------------------------
__global__ __launch_bounds__(256)
void snn_scan_kernel(float* __restrict__ Y)
{
    const int b = blockIdx.x;
    const int o = threadIdx.x;
    const float* hp = g_h + (size_t)b * T_ * O_ + o;
    float*       yp = Y   + (size_t)b * T_ * O_ + o;

    float flt = 0.0f, out = 0.0f;

    #pragma unroll 1
    for (int t = 0; t < T_; t += 4) {
        float h0 = hp[0 * O_];
        float h1 = hp[1 * O_];
        float h2 = hp[2 * O_];
        float h3 = hp[3 * O_];

        float o0 = fmaf(BETA, out, flt); flt = fmaf(ALPHA, flt, h0);
        float o1 = fmaf(BETA, o0,  flt); flt = fmaf(ALPHA, flt, h1);
        float o2 = fmaf(BETA, o1,  flt); flt = fmaf(ALPHA, flt, h2);
        float o3 = fmaf(BETA, o2,  flt); flt = fmaf(ALPHA, flt, h3);
        out = o3;

        yp[0 * O_] = o0;
        yp[1 * O_] = o1;
        yp[2 * O_] = o2;
        yp[3 * O_] = o3;

        hp += 4 * O_;
        yp += 4 * O_;
    }
}

// ---------------------------------------------------------------------------
extern "C" void kernel_launch(void* const* d_in, const int* in_sizes, int n_in,
                              void* d_out, int out_size)
{
    const float* inputs = (const float*)d_in[0];   // (B,T,I) fp32
    const float* W      = (const float*)d_in[1];   // (O,I)   fp32
    float* out          = (float*)d_out;           // (B,T,O) fp32

    dim3 ggrid(O_ / BN, M_ / BM);                  // (2, 500)
    snn_gemm_kernel<<<ggrid, 256>>>(inputs, W);
    snn_scan_kernel<<<B_, 256>>>(out);
}

// round 7
// speedup vs baseline: 1.7313x; 1.7313x over previous
#include <cuda_runtime.h>
#include <cuda_bf16.h>
#include <cstdint>

// ---------------------------------------------------------------- constants
#define B_   64
#define T_   1000
#define I_   512
#define O_   256
#define M_   (B_ * T_)          // 64000
#define ALPHA 0.95f
#define BETA  0.9f

// GEMM tiling
#define BM      128
#define BN      128
#define BKC     64              // K per chunk
#define NCHUNK  (I_ / BKC)      // 8
#define LDROW   144             // padded row stride in bytes (72 bf16)

// Scan chunking
#define SC_C    8
#define SC_L    (T_ / SC_C)     // 125

// SMEM layout (bytes): 4 tiles of 128 rows x 144B
#define SM_AHI  0
#define SM_ALO  18432
#define SM_WHI  36864
#define SM_WLO  55296
#define SM_GTOT 73728

// ---------------------------------------------------------------- scratch
__device__ float g_h[(size_t)M_ * O_];                  // GEMM output
__device__ __nv_bfloat16 g_Whi[(size_t)O_ * I_];        // W hi (row-major [O][I])
__device__ __nv_bfloat16 g_Wlo[(size_t)O_ * I_];        // W lo

// ---------------------------------------------------------------- helpers
__device__ __forceinline__ uint32_t smem_u32(const void* p) {
    uint32_t a;
    asm("{ .reg .u64 t; cvta.to.shared.u64 t, %1; cvt.u32.u64 %0, t; }"
        : "=r"(a) : "l"(p));
    return a;
}
__device__ __forceinline__ void ldsm4(uint32_t* r, uint32_t a) {
    asm volatile("ldmatrix.sync.aligned.m8n8.x4.shared.b16 {%0,%1,%2,%3}, [%4];"
        : "=r"(r[0]), "=r"(r[1]), "=r"(r[2]), "=r"(r[3]) : "r"(a));
}
__device__ __forceinline__ void cp16(uint32_t d, const void* s) {
    asm volatile("cp.async.cg.shared.global [%0], [%1], 16;" :: "r"(d), "l"(s));
}
__device__ __forceinline__ void mma16816(float* d, const uint32_t* a,
                                         const uint32_t* b) {
    asm volatile("mma.sync.aligned.m16n8k16.row.col.f32.bf16.bf16.f32 "
        "{%0,%1,%2,%3}, {%4,%5,%6,%7}, {%8,%9}, {%0,%1,%2,%3};"
        : "+f"(d[0]), "+f"(d[1]), "+f"(d[2]), "+f"(d[3])
        : "r"(a[0]), "r"(a[1]), "r"(a[2]), "r"(a[3]), "r"(b[0]), "r"(b[1]));
}

// ---------------------------------------------------------------- W pre-split
__global__ void snn_wsplit(const float* __restrict__ W)
{
    int idx = blockIdx.x * blockDim.x + threadIdx.x;
    if (idx >= O_ * I_) return;
    float x = W[idx];
    __nv_bfloat16 hi = __float2bfloat16(x);
    __nv_bfloat16 lo = __float2bfloat16(x - __bfloat162float(hi));
    g_Whi[idx] = hi;
    g_Wlo[idx] = lo;
}

// ---------------------------------------------------------------- mma GEMM
// C[128,128] per CTA. 3-term bf16 split: Ahi*Whi + Ahi*Wlo + Alo*Whi.
// A: LDG->reg prefetch, convert+STS. W: cp.async from pre-split gmem.
__global__ __launch_bounds__(256, 1)
void snn_gemm_mma(const float* __restrict__ A)
{
    extern __shared__ char smem[];
    const uint32_t sb = smem_u32(smem);
    const int tid  = threadIdx.x;
    const int lane = tid & 31;
    const int wid  = tid >> 5;
    const int wm   = wid >> 2;                  // 0..1  (M warps)
    const int wn   = wid & 3;                   // 0..3  (N warps)
    const int m0   = blockIdx.y * BM;
    const int n0   = blockIdx.x * BN;

    // A staging: thread owns row = tid>>1, k-half = (tid&1)*32
    const int arow = tid >> 1;
    const int akh  = (tid & 1) * 32;
    const float* Ap = A + (size_t)(m0 + arow) * I_ + akh;
    char* a_hi_p = smem + SM_AHI + arow * LDROW + akh * 2;
    char* a_lo_p = smem + SM_ALO + arow * LDROW + akh * 2;

    // ldmatrix per-lane coords
    const int a_r = wm * 64 + (lane & 15);
    const int a_c = (lane >> 4) * 8;
    const int b_r = wn * 32 + (lane & 15);
    const int b_c = (lane >> 4) * 8;

    float acc[4][4][4];
    #pragma unroll
    for (int mb = 0; mb < 4; mb++)
        #pragma unroll
        for (int j = 0; j < 4; j++)
            #pragma unroll
            for (int q = 0; q < 4; q++) acc[mb][j][q] = 0.0f;

    // prefetch A chunk 0
    float4 av[8];
    #pragma unroll
    for (int i = 0; i < 8; i++) av[i] = ((const float4*)Ap)[i];

    #pragma unroll 1
    for (int chunk = 0; chunk < NCHUNK; chunk++) {
        // ---- STS A (fp32 -> bf16 hi/lo)
        #pragma unroll
        for (int i = 0; i < 8; i++) {
            float4 v = av[i];
            __nv_bfloat162 h01 = __floats2bfloat162_rn(v.x, v.y);
            __nv_bfloat162 h23 = __floats2bfloat162_rn(v.z, v.w);
            __nv_bfloat162 l01 = __floats2bfloat162_rn(v.x - __low2float(h01),
                                                       v.y - __high2float(h01));
            __nv_bfloat162 l23 = __floats2bfloat162_rn(v.z - __low2float(h23),
                                                       v.w - __high2float(h23));
            *(uint2*)(a_hi_p + i * 8) =
                make_uint2(*(uint32_t*)&h01, *(uint32_t*)&h23);
            *(uint2*)(a_lo_p + i * 8) =
                make_uint2(*(uint32_t*)&l01, *(uint32_t*)&l23);
        }
        // ---- cp.async W chunk (hi + lo), 128 rows x 64 bf16 each
        #pragma unroll
        for (int i = 0; i < 4; i++) {
            int idx = tid + i * 256;
            int row = idx >> 3, c = idx & 7;
            uint32_t doff = (uint32_t)row * LDROW + c * 16;
            size_t soff = (size_t)(n0 + row) * I_ + chunk * BKC + c * 8;
            cp16(sb + SM_WHI + doff, g_Whi + soff);
            cp16(sb + SM_WLO + doff, g_Wlo + soff);
        }
        asm volatile("cp.async.commit_group;" ::: "memory");

        // ---- prefetch next A chunk
        if (chunk + 1 < NCHUNK) {
            const float4* nx = (const float4*)(Ap + (chunk + 1) * BKC);
            #pragma unroll
            for (int i = 0; i < 8; i++) av[i] = nx[i];
        }

        asm volatile("cp.async.wait_group 0;" ::: "memory");
        __syncthreads();

        // ---- compute 4 k16 steps
        #pragma unroll
        for (int ks = 0; ks < 4; ks++) {
            const int kb = ks * 16;
            uint32_t ahi[4][4], alo[4][4];
            #pragma unroll
            for (int mb = 0; mb < 4; mb++) {
                uint32_t ra = sb + SM_AHI
                            + (uint32_t)(a_r + mb * 16) * LDROW + (kb + a_c) * 2;
                ldsm4(ahi[mb], ra);
                ldsm4(alo[mb], ra + (SM_ALO - SM_AHI));
            }
            uint32_t bhi[4][2], blo[4][2];
            #pragma unroll
            for (int g = 0; g < 2; g++) {
                uint32_t rb = sb + SM_WHI
                            + (uint32_t)(b_r + g * 16) * LDROW + (kb + b_c) * 2;
                uint32_t r[4];
                ldsm4(r, rb);
                bhi[g*2][0] = r[0]; bhi[g*2][1] = r[2];
                bhi[g*2+1][0] = r[1]; bhi[g*2+1][1] = r[3];
                ldsm4(r, rb + (SM_WLO - SM_WHI));
                blo[g*2][0] = r[0]; blo[g*2][1] = r[2];
                blo[g*2+1][0] = r[1]; blo[g*2+1][1] = r[3];
            }
            #pragma unroll
            for (int mb = 0; mb < 4; mb++)
                #pragma unroll
                for (int j = 0; j < 4; j++) {
                    mma16816(acc[mb][j], ahi[mb], bhi[j]);
                    mma16816(acc[mb][j], ahi[mb], blo[j]);
                    mma16816(acc[mb][j], alo[mb], bhi[j]);
                }
        }
        __syncthreads();
    }

    // ---- epilogue: fragment -> g_h (lane owns rows l/4, l/4+8; cols 2(l%4)+{0,1})
    #pragma unroll
    for (int mb = 0; mb < 4; mb++) {
        int row = m0 + wm * 64 + mb * 16 + (lane >> 2);
        #pragma unroll
        for (int j = 0; j < 4; j++) {
            int col = n0 + wn * 32 + j * 8 + (lane & 3) * 2;
            float* p = g_h + (size_t)row * O_ + col;
            *(float2*)p            = make_float2(acc[mb][j][0], acc[mb][j][1]);
            *(float2*)(p + 8 * O_) = make_float2(acc[mb][j][2], acc[mb][j][3]);
        }
    }
}

// ---------------------------------------------------------------- parallel scan
// Chunked affine-scan: phase1 zero-init chunk scans, phase2 combine (8 states),
// phase3 exact re-scan with true init. Block = 32 chains x 8 chunks.
__global__ __launch_bounds__(256)
void snn_scan2(float* __restrict__ Y)
{
    __shared__ float ef[SC_C][32], eo[SC_C][32];
    __shared__ float qf[SC_C][32], qo[SC_C][32];

    const int tid = threadIdx.x;
    const int ch  = tid & 31;
    const int c   = tid >> 5;
    const int chain = blockIdx.x * 32 + ch;
    const int b = chain >> 8;
    const int o = chain & (O_ - 1);

    const float* hp = g_h + ((size_t)b * T_ + (size_t)c * SC_L) * O_ + o;

    float f = 0.0f, u = 0.0f;
    #pragma unroll 5
    for (int j = 0; j < SC_L; j++) {
        float h  = hp[(size_t)j * O_];
        float nu = fmaf(BETA, u, f);
        f = fmaf(ALPHA, f, h);
        u = nu;
    }
    ef[c][ch] = f;
    eo[c][ch] = u;
    __syncthreads();

    if (tid < 32) {
        float AL = 1.0f, BL = 1.0f;
        #pragma unroll
        for (int i = 0; i < SC_L; i++) { AL *= ALPHA; BL *= BETA; }
        const float GL = (AL - BL) * (1.0f / (ALPHA - BETA));
        float sf = 0.0f, su = 0.0f;
        #pragma unroll
        for (int cc = 0; cc < SC_C; cc++) {
            qf[cc][tid] = sf;
            qo[cc][tid] = su;
            float nsf = AL * sf + ef[cc][tid];
            float nsu = GL * sf + BL * su + eo[cc][tid];
            sf = nsf;
            su = nsu;
        }
    }
    __syncthreads();

    f = qf[c][ch];
    u = qo[c][ch];
    float* yp = Y + ((size_t)b * T_ + (size_t)c * SC_L) * O_ + o;
    #pragma unroll 5
    for (int j = 0; j < SC_L; j++) {
        float h  = hp[(size_t)j * O_];
        float nu = fmaf(BETA, u, f);
        f = fmaf(ALPHA, f, h);
        u = nu;
        yp[(size_t)j * O_] = nu;
    }
}

// ----------------------------------------------------------------
extern "C" void kernel_launch(void* const* d_in, const int* in_sizes, int n_in,
                              void* d_out, int out_size)
{
    const float* inputs = (const float*)d_in[0];   // (B,T,I) fp32
    const float* W      = (const float*)d_in[1];   // (O,I)   fp32
    float* out          = (float*)d_out;           // (B,T,O) fp32

    cudaFuncSetAttribute(snn_gemm_mma,
                         cudaFuncAttributeMaxDynamicSharedMemorySize, SM_GTOT);

    snn_wsplit<<<(O_ * I_ + 255) / 256, 256>>>(W);
    dim3 ggrid(O_ / BN, M_ / BM);                  // (2, 500)
    snn_gemm_mma<<<ggrid, 256, SM_GTOT>>>(inputs);
    snn_scan2<<<(B_ * O_) / 32, 256>>>(out);
}

// round 8
// speedup vs baseline: 2.0376x; 1.1769x over previous
#include <cuda_runtime.h>
#include <cuda_bf16.h>
#include <cstdint>

// ---------------------------------------------------------------- constants
#define B_   64
#define T_   1000
#define I_   512
#define O_   256
#define M_   (B_ * T_)          // 64000
#define ALPHA 0.95f
#define BETA  0.9f

// GEMM tiling
#define BM      128
#define BN      128
#define BKC     64              // K per chunk
#define NCHUNK  (I_ / BKC)      // 8
#define LDROW   144             // padded row stride in bytes (72 bf16)

// Scan chunking
#define SC_C    8
#define SC_L    (T_ / SC_C)     // 125

// SMEM layout (bytes): 4 tiles of 128 rows x 144B
#define SM_AHI  0
#define SM_ALO  18432
#define SM_WHI  36864
#define SM_WLO  55296
#define SM_GTOT 73728

// ---------------------------------------------------------------- scratch
__device__ float g_h[(size_t)M_ * O_];                  // GEMM output
__device__ __nv_bfloat16 g_Whi[(size_t)O_ * I_];        // W hi (row-major [O][I])
__device__ __nv_bfloat16 g_Wlo[(size_t)O_ * I_];        // W lo

// ---------------------------------------------------------------- helpers
__device__ __forceinline__ uint32_t smem_u32(const void* p) {
    uint32_t a;
    asm("{ .reg .u64 t; cvta.to.shared.u64 t, %1; cvt.u32.u64 %0, t; }"
        : "=r"(a) : "l"(p));
    return a;
}
__device__ __forceinline__ void ldsm4(uint32_t* r, uint32_t a) {
    asm volatile("ldmatrix.sync.aligned.m8n8.x4.shared.b16 {%0,%1,%2,%3}, [%4];"
        : "=r"(r[0]), "=r"(r[1]), "=r"(r[2]), "=r"(r[3]) : "r"(a));
}
__device__ __forceinline__ void cp16(uint32_t d, const void* s) {
    asm volatile("cp.async.cg.shared.global [%0], [%1], 16;" :: "r"(d), "l"(s));
}
__device__ __forceinline__ void mma16816(float* d, const uint32_t* a,
                                         const uint32_t* b) {
    asm volatile("mma.sync.aligned.m16n8k16.row.col.f32.bf16.bf16.f32 "
        "{%0,%1,%2,%3}, {%4,%5,%6,%7}, {%8,%9}, {%0,%1,%2,%3};"
        : "+f"(d[0]), "+f"(d[1]), "+f"(d[2]), "+f"(d[3])
        : "r"(a[0]), "r"(a[1]), "r"(a[2]), "r"(a[3]), "r"(b[0]), "r"(b[1]));
}

// ---------------------------------------------------------------- W pre-split
__global__ void snn_wsplit(const float* __restrict__ W)
{
    int idx = blockIdx.x * blockDim.x + threadIdx.x;
    if (idx >= O_ * I_) return;
    float x = W[idx];
    __nv_bfloat16 hi = __float2bfloat16(x);
    __nv_bfloat16 lo = __float2bfloat16(x - __bfloat162float(hi));
    g_Whi[idx] = hi;
    g_Wlo[idx] = lo;
}

// ---------------------------------------------------------------- mma GEMM
// C[128,128] per CTA. 3-term bf16 split: Ahi*Whi + Ahi*Wlo + Alo*Whi.
// occ=2: CTA pairs on an SM mutually hide staging behind MMA.
__global__ __launch_bounds__(256, 2)
void snn_gemm_mma(const float* __restrict__ A)
{
    extern __shared__ char smem[];
    const uint32_t sb = smem_u32(smem);
    const int tid  = threadIdx.x;
    const int lane = tid & 31;
    const int wid  = tid >> 5;
    const int wm   = wid >> 2;                  // 0..1  (M warps)
    const int wn   = wid & 3;                   // 0..3  (N warps)
    const int m0   = blockIdx.y * BM;
    const int n0   = blockIdx.x * BN;

    // A staging: thread owns row = tid>>1, k-half = (tid&1)*32
    const int arow = tid >> 1;
    const int akh  = (tid & 1) * 32;
    const float* Ap = A + (size_t)(m0 + arow) * I_ + akh;
    char* a_hi_p = smem + SM_AHI + arow * LDROW + akh * 2;
    char* a_lo_p = smem + SM_ALO + arow * LDROW + akh * 2;

    // ldmatrix per-lane coords
    const int a_r = wm * 64 + (lane & 15);
    const int a_c = (lane >> 4) * 8;
    const int b_r = wn * 32 + (lane & 15);
    const int b_c = (lane >> 4) * 8;

    float acc[4][4][4];
    #pragma unroll
    for (int mb = 0; mb < 4; mb++)
        #pragma unroll
        for (int j = 0; j < 4; j++)
            #pragma unroll
            for (int q = 0; q < 4; q++) acc[mb][j][q] = 0.0f;

    #pragma unroll 1
    for (int chunk = 0; chunk < NCHUNK; chunk++) {
        // ---- cp.async W chunk (hi + lo), 128 rows x 64 bf16 each
        #pragma unroll
        for (int i = 0; i < 4; i++) {
            int idx = tid + i * 256;
            int row = idx >> 3, c = idx & 7;
            uint32_t doff = (uint32_t)row * LDROW + c * 16;
            size_t soff = (size_t)(n0 + row) * I_ + chunk * BKC + c * 8;
            cp16(sb + SM_WHI + doff, g_Whi + soff);
            cp16(sb + SM_WLO + doff, g_Wlo + soff);
        }
        asm volatile("cp.async.commit_group;" ::: "memory");

        // ---- A: LDG -> bf16 hi/lo -> STS (no big prefetch array; occ-2 hides lat)
        const float4* Ac = (const float4*)(Ap + chunk * BKC);
        #pragma unroll
        for (int i = 0; i < 8; i++) {
            float4 v = Ac[i];
            __nv_bfloat162 h01 = __floats2bfloat162_rn(v.x, v.y);
            __nv_bfloat162 h23 = __floats2bfloat162_rn(v.z, v.w);
            __nv_bfloat162 l01 = __floats2bfloat162_rn(v.x - __low2float(h01),
                                                       v.y - __high2float(h01));
            __nv_bfloat162 l23 = __floats2bfloat162_rn(v.z - __low2float(h23),
                                                       v.w - __high2float(h23));
            *(uint2*)(a_hi_p + i * 8) =
                make_uint2(*(uint32_t*)&h01, *(uint32_t*)&h23);
            *(uint2*)(a_lo_p + i * 8) =
                make_uint2(*(uint32_t*)&l01, *(uint32_t*)&l23);
        }

        asm volatile("cp.async.wait_group 0;" ::: "memory");
        __syncthreads();

        // ---- compute 4 k16 steps
        #pragma unroll
        for (int ks = 0; ks < 4; ks++) {
            const int kb = ks * 16;
            // B fragments first (resident across the mb loop)
            uint32_t bhi[4][2], blo[4][2];
            #pragma unroll
            for (int g = 0; g < 2; g++) {
                uint32_t rb = sb + SM_WHI
                            + (uint32_t)(b_r + g * 16) * LDROW + (kb + b_c) * 2;
                uint32_t r[4];
                ldsm4(r, rb);
                bhi[g*2][0] = r[0]; bhi[g*2][1] = r[2];
                bhi[g*2+1][0] = r[1]; bhi[g*2+1][1] = r[3];
                ldsm4(r, rb + (SM_WLO - SM_WHI));
                blo[g*2][0] = r[0]; blo[g*2][1] = r[2];
                blo[g*2+1][0] = r[1]; blo[g*2+1][1] = r[3];
            }
            // A fragments per mb (short live range keeps regs <= 128)
            #pragma unroll
            for (int mb = 0; mb < 4; mb++) {
                uint32_t ahi[4], alo[4];
                uint32_t ra = sb + SM_AHI
                            + (uint32_t)(a_r + mb * 16) * LDROW + (kb + a_c) * 2;
                ldsm4(ahi, ra);
                ldsm4(alo, ra + (SM_ALO - SM_AHI));
                #pragma unroll
                for (int j = 0; j < 4; j++) {
                    mma16816(acc[mb][j], ahi, bhi[j]);
                    mma16816(acc[mb][j], ahi, blo[j]);
                    mma16816(acc[mb][j], alo, bhi[j]);
                }
            }
        }
        __syncthreads();
    }

    // ---- epilogue: fragment -> g_h (lane owns rows l/4, l/4+8; cols 2(l%4)+{0,1})
    #pragma unroll
    for (int mb = 0; mb < 4; mb++) {
        int row = m0 + wm * 64 + mb * 16 + (lane >> 2);
        #pragma unroll
        for (int j = 0; j < 4; j++) {
            int col = n0 + wn * 32 + j * 8 + (lane & 3) * 2;
            float* p = g_h + (size_t)row * O_ + col;
            *(float2*)p            = make_float2(acc[mb][j][0], acc[mb][j][1]);
            *(float2*)(p + 8 * O_) = make_float2(acc[mb][j][2], acc[mb][j][3]);
        }
    }
}

// ---------------------------------------------------------------- parallel scan
// Chunked affine-scan: phase1 zero-init chunk scans, phase2 combine (8 states),
// phase3 exact re-scan with true init. Block = 32 chains x 8 chunks.
__global__ __launch_bounds__(256)
void snn_scan2(float* __restrict__ Y)
{
    __shared__ float ef[SC_C][32], eo[SC_C][32];
    __shared__ float qf[SC_C][32], qo[SC_C][32];

    const int tid = threadIdx.x;
    const int ch  = tid & 31;
    const int c   = tid >> 5;
    const int chain = blockIdx.x * 32 + ch;
    const int b = chain >> 8;
    const int o = chain & (O_ - 1);

    const float* hp = g_h + ((size_t)b * T_ + (size_t)c * SC_L) * O_ + o;

    float f = 0.0f, u = 0.0f;
    #pragma unroll 5
    for (int j = 0; j < SC_L; j++) {
        float h  = hp[(size_t)j * O_];
        float nu = fmaf(BETA, u, f);
        f = fmaf(ALPHA, f, h);
        u = nu;
    }
    ef[c][ch] = f;
    eo[c][ch] = u;
    __syncthreads();

    if (tid < 32) {
        float AL = 1.0f, BL = 1.0f;
        #pragma unroll
        for (int i = 0; i < SC_L; i++) { AL *= ALPHA; BL *= BETA; }
        const float GL = (AL - BL) * (1.0f / (ALPHA - BETA));
        float sf = 0.0f, su = 0.0f;
        #pragma unroll
        for (int cc = 0; cc < SC_C; cc++) {
            qf[cc][tid] = sf;
            qo[cc][tid] = su;
            float nsf = AL * sf + ef[cc][tid];
            float nsu = GL * sf + BL * su + eo[cc][tid];
            sf = nsf;
            su = nsu;
        }
    }
    __syncthreads();

    f = qf[c][ch];
    u = qo[c][ch];
    float* yp = Y + ((size_t)b * T_ + (size_t)c * SC_L) * O_ + o;
    #pragma unroll 5
    for (int j = 0; j < SC_L; j++) {
        float h  = hp[(size_t)j * O_];
        float nu = fmaf(BETA, u, f);
        f = fmaf(ALPHA, f, h);
        u = nu;
        yp[(size_t)j * O_] = nu;
    }
}

// ----------------------------------------------------------------
extern "C" void kernel_launch(void* const* d_in, const int* in_sizes, int n_in,
                              void* d_out, int out_size)
{
    const float* inputs = (const float*)d_in[0];   // (B,T,I) fp32
    const float* W      = (const float*)d_in[1];   // (O,I)   fp32
    float* out          = (float*)d_out;           // (B,T,O) fp32

    cudaFuncSetAttribute(snn_gemm_mma,
                         cudaFuncAttributeMaxDynamicSharedMemorySize, SM_GTOT);

    snn_wsplit<<<(O_ * I_ + 255) / 256, 256>>>(W);
    dim3 ggrid(O_ / BN, M_ / BM);                  // (2, 500)
    snn_gemm_mma<<<ggrid, 256, SM_GTOT>>>(inputs);
    snn_scan2<<<(B_ * O_) / 32, 256>>>(out);
}